// round 8
// baseline (speedup 1.0000x reference)
#include <cuda_runtime.h>
#include <cuda_bf16.h>

// InvertiblePWL, persistent single-wave kernel, depth-2 pipelined loop:
//   out = eps * A[idx] + B[idx]
//   idx via magic-number floor: clamp e to [-5.05, 5.0],
//     r1 = fma.rm(e, 9.9, 49.5)   in [-0.495, 99]
//     r2 = add.rm(r1, 12582912.0) -> exact floor (ULP=1 region)
//     idx = float_bits(r2) - 1262485503   in [0, 100]   (+1 folded in)
//   A[i] = exp(p[i]) + 0.001
//   B[i] = (b0 + pref_excl[i]) - points[max(i-1,0)] * A[i]
// Warp 0 builds the 101-entry table once per CTA (single warp scan).

#define N_BINS 100
#define TPB    256
#define GRID   1184         // 8 CTAs/SM * 148 SMs -> one persistent wave

__device__ __forceinline__ float pwl_one(float e, const float2* __restrict__ sAB) {
    const float ec = fminf(fmaxf(e, -5.05f), 5.0f);
    const float r1 = __fmaf_rd(ec, 9.9f, 49.5f);
    const float r2 = __fadd_rd(r1, 12582912.0f);       // 1.5*2^23, ULP=1
    const int  idx = __float_as_int(r2) - 1262485503;  // floor(raw)+1 in [0,100]
    const float2 ab = sAB[idx];
    return fmaf(e, ab.x, ab.y);
}

__global__ void __launch_bounds__(TPB)
pwl_kernel(const float4* __restrict__ eps,
           const float*  __restrict__ p,
           const float*  __restrict__ b,
           const float*  __restrict__ points,
           float4* __restrict__ out, int n4) {
    __shared__ float2 sAB[N_BINS + 1];

    const int t = threadIdx.x;

    // ---- Warp 0: build table. Lane l owns indices 4l..4l+3 (0..127).
    if (t < 32) {
        const float int_len = 10.0f / 99.0f;
        const int i0 = 4 * t;
        const float b0 = b[0];

        float pv[4], pts[4];
#pragma unroll
        for (int k = 0; k < 4; k++) {
            const int idx = i0 + k;
            pv[k]  = (idx <= N_BINS) ? p[idx] : 0.0f;
            const int s = (idx > 0) ? (idx - 1) : 0;
            pts[k] = (idx <= N_BINS) ? points[s] : 0.0f;
        }

        float a[4], d[4];
#pragma unroll
        for (int k = 0; k < 4; k++) {
            const int idx = i0 + k;
            a[k] = expf(pv[k]) + 0.001f;
            d[k] = (idx >= 1 && idx <= N_BINS - 1) ? int_len * a[k] : 0.0f;
        }

        float l1 = d[0] + d[1];
        float lsum = l1 + d[2] + d[3];

        float incl = lsum;
#pragma unroll
        for (int o = 1; o < 32; o <<= 1) {
            float u = __shfl_up_sync(0xFFFFFFFFu, incl, o);
            if (t >= o) incl += u;
        }
        const float lane_excl = incl - lsum;

        float ex[4];
        ex[0] = lane_excl;
        ex[1] = lane_excl + d[0];
        ex[2] = lane_excl + l1;
        ex[3] = lane_excl + l1 + d[2];

#pragma unroll
        for (int k = 0; k < 4; k++) {
            const int idx = i0 + k;
            if (idx <= N_BINS)
                sAB[idx] = make_float2(a[k], (b0 + ex[k]) - pts[k] * a[k]);
        }
    }

    // ---- Depth-2 prefetch before the barrier (hides table build).
    const int stride = GRID * TPB;
    int i0 = blockIdx.x * TPB + t;
    int i1 = i0 + stride;
    float4 cur, nxt;
    if (i0 < n4) cur = eps[i0];
    if (i1 < n4) nxt = eps[i1];

    __syncthreads();

    // ---- Pipelined grid-stride loop: always two loads in flight.
    while (i0 < n4) {
        const int i2 = i1 + stride;
        float4 fut;
        if (i2 < n4) fut = eps[i2];

        float4 r;
        r.x = pwl_one(cur.x, sAB);
        r.y = pwl_one(cur.y, sAB);
        r.z = pwl_one(cur.z, sAB);
        r.w = pwl_one(cur.w, sAB);
        out[i0] = r;

        cur = nxt;
        nxt = fut;
        i0 = i1;
        i1 = i2;
    }
}

extern "C" void kernel_launch(void* const* d_in, const int* in_sizes, int n_in,
                              void* d_out, int out_size) {
    const float* eps    = (const float*)d_in[0];   // [4000000]
    const float* p      = (const float*)d_in[1];   // [101]
    const float* b      = (const float*)d_in[2];   // [1]
    const float* points = (const float*)d_in[3];   // [100]
    float* out = (float*)d_out;

    const int n4 = out_size / 4;                   // 1,000,000
    pwl_kernel<<<GRID, TPB>>>((const float4*)eps, p, b, points,
                              (float4*)out, n4);
}